// round 7
// baseline (speedup 1.0000x reference)
#include <cuda_runtime.h>
#include <cuda_bf16.h>
#include <math.h>
#include <stdint.h>

#define NVEC 12
#define CIN  8
#define COUT 8
#define DIM  64
#define VOX  (DIM*DIM*DIM)      // 262144
#define CH   (CIN*NVEC)         // 96

// Device-global scratch (allocation-free per harness rules)
__device__ float g_sw[CH * 125];            // depthwise taps: [c][k]
__device__ float g_fwm[CH * CH];            // mixing matrix: [oc][fv]
__device__ float g_y[(size_t)2 * CH * VOX]; // depthwise conv output (192 MiB)

__device__ __forceinline__ float gelu_exact(float v) {
    return 0.5f * v * (1.0f + erff(v * 0.70710678118654752440f));
}

// ---------------------------------------------------------------------------
// Kernel W (light): 1 thread per attr row. 1500 spatial rows (each -> 8 taps),
// 144 fiber rows (each -> 64 mixing entries). grid 13 x 128 = 1664 threads.
// ---------------------------------------------------------------------------
__global__ __launch_bounds__(128) void weights_kernel(
    const float* __restrict__ sp, const float* __restrict__ sph,
    const float* __restrict__ bw1, const float* __restrict__ bb1,
    const float* __restrict__ bw2, const float* __restrict__ bb2,
    const float* __restrict__ bw3,
    const float* __restrict__ fw1, const float* __restrict__ fb1,
    const float* __restrict__ fw2, const float* __restrict__ fb2,
    const float* __restrict__ fw3)
{
    int tid = blockIdx.x * blockDim.x + threadIdx.x;

    if (tid < 1500) {
        int r = tid;
        float s0 = sp[2 * r], s1 = sp[2 * r + 1];
        float a[14];
        a[0] = s0; a[1] = s1;
        a[2] = s0 * s0; a[3] = s0 * s1; a[4] = s1 * s0; a[5] = s1 * s1;
        #pragma unroll
        for (int i = 0; i < 4; i++) { a[6 + 2*i] = a[2 + i] * s0; a[7 + 2*i] = a[2 + i] * s1; }
        float h1[8], h2[8];
        #pragma unroll
        for (int j = 0; j < 8; j++) {
            float s = bb1[j];
            #pragma unroll
            for (int i = 0; i < 14; i++) s += bw1[j * 14 + i] * a[i];
            h1[j] = gelu_exact(s);
        }
        #pragma unroll
        for (int j = 0; j < 8; j++) {
            float s = bb2[j];
            #pragma unroll
            for (int i = 0; i < 8; i++) s += bw2[j * 8 + i] * h1[i];
            h2[j] = gelu_exact(s);
        }
        int k = r / 12, v = r % 12;
        #pragma unroll
        for (int f = 0; f < 8; f++) {
            float o = 0.f;
            #pragma unroll
            for (int i = 0; i < 8; i++) o += bw3[f * 8 + i] * h2[i];
            g_sw[(f * 12 + v) * 125 + k] = o;
        }
    } else if (tid < 1644) {
        int r = tid - 1500;
        float c0 = sph[r];
        float a0 = c0, a1 = c0 * c0, a2 = c0 * c0 * c0;
        float h1[8], h2[8];
        #pragma unroll
        for (int j = 0; j < 8; j++) {
            float s = fb1[j] + fw1[j*3+0]*a0 + fw1[j*3+1]*a1 + fw1[j*3+2]*a2;
            h1[j] = gelu_exact(s);
        }
        #pragma unroll
        for (int j = 0; j < 8; j++) {
            float s = fb2[j];
            #pragma unroll
            for (int i = 0; i < 8; i++) s += fw2[j * 8 + i] * h1[i];
            h2[j] = gelu_exact(s);
        }
        int v = r / 12, w = r % 12;
        #pragma unroll
        for (int col = 0; col < 64; col++) {
            float o = 0.f;
            #pragma unroll
            for (int i = 0; i < 8; i++) o += fw3[col * 8 + i] * h2[i];
            int f = col >> 3, g = col & 7;
            g_fwm[(g * 12 + w) * CH + (f * 12 + v)] = o;   // [oc][fv]
        }
    }
}

// ---------------------------------------------------------------------------
// Kernel A: depthwise 5x5x5 conv (cross-correlation, SAME padding).
// 8x8x32 tiles, 256 threads, one full 8-z column per thread.
// ---------------------------------------------------------------------------
__global__ __launch_bounds__(256) void conv_kernel(const float* __restrict__ x)
{
    __shared__ __align__(16) float s_x[12 * 12 * 36];   // pitch-36 z rows
    __shared__ __align__(16) float s_k[25 * 8];         // taps, 8/pos padded

    int tile = blockIdx.x;            // 0..127
    int c    = blockIdx.y;            // 0..95
    int b    = blockIdx.z;            // 0..1
    int tx = tile >> 4, ty = (tile >> 1) & 7, tz = tile & 1;
    int t = threadIdx.x;

    if (t < 125) {
        int kx = t / 25, rr = t % 25, ky = rr / 5, kz = rr % 5;
        s_k[(kx * 5 + ky) * 8 + kz] = g_sw[c * 125 + t];
    }

    // ---- halo load: 12 x 12 x 36 ----
    const float* xb = x + (size_t)(b * CH + c) * VOX;
    int gx0 = tx * 8 - 2, gy0 = ty * 8 - 2, gz0 = tz * 32 - 2;
    for (int i = t; i < 5184; i += 256) {
        int lx = i / 432, r = i % 432, ly = r / 36, lz = r % 36;
        int gx = gx0 + lx, gy = gy0 + ly, gz = gz0 + lz;
        float vv = 0.f;
        if ((unsigned)gx < 64u && (unsigned)gy < 64u && (unsigned)gz < 64u)
            vv = xb[(gx << 12) + (gy << 6) + gz];
        s_x[i] = vv;
    }
    __syncthreads();

    int xy = t >> 2;
    int ox = xy >> 3, oy = xy & 7;
    int zo = (t & 3) * 8;

    float acc0 = 0.f, acc1 = 0.f, acc2 = 0.f, acc3 = 0.f;
    float acc4 = 0.f, acc5 = 0.f, acc6 = 0.f, acc7 = 0.f;
    #pragma unroll
    for (int kx = 0; kx < 5; kx++) {
        #pragma unroll
        for (int ky = 0; ky < 5; ky++) {
            const float* xp = &s_x[((ox + kx) * 12 + (oy + ky)) * 36 + zo];
            float4 vA = *(const float4*)xp;
            float4 vB = *(const float4*)(xp + 4);
            float4 vC = *(const float4*)(xp + 8);
            float f0 = vA.x, f1 = vA.y, f2 = vA.z, f3 = vA.w;
            float f4 = vB.x, f5 = vB.y, f6 = vB.z, f7 = vB.w;
            float f8 = vC.x, f9 = vC.y, f10 = vC.z, f11 = vC.w;
            const float* kp = &s_k[(kx * 5 + ky) * 8];
            float4 tv = *(const float4*)kp;
            float t4 = kp[4];
            acc0 += f0*tv.x + f1*tv.y + f2*tv.z + f3*tv.w + f4*t4;
            acc1 += f1*tv.x + f2*tv.y + f3*tv.z + f4*tv.w + f5*t4;
            acc2 += f2*tv.x + f3*tv.y + f4*tv.z + f5*tv.w + f6*t4;
            acc3 += f3*tv.x + f4*tv.y + f5*tv.z + f6*tv.w + f7*t4;
            acc4 += f4*tv.x + f5*tv.y + f6*tv.z + f7*tv.w + f8*t4;
            acc5 += f5*tv.x + f6*tv.y + f7*tv.z + f8*tv.w + f9*t4;
            acc6 += f6*tv.x + f7*tv.y + f8*tv.z + f9*tv.w + f10*t4;
            acc7 += f7*tv.x + f8*tv.y + f9*tv.z + f10*tv.w + f11*t4;
        }
    }
    size_t oidx = (size_t)(b * CH + c) * VOX
                + (size_t)((tx * 8 + ox) << 12) + ((ty * 8 + oy) << 6) + tz * 32 + zo;
    *(float4*)&g_y[oidx]     = make_float4(acc0, acc1, acc2, acc3);
    *(float4*)&g_y[oidx + 4] = make_float4(acc4, acc5, acc6, acc7);
}

// ---------------------------------------------------------------------------
// Kernel B: per-voxel 96x96 channel mixing on mma.sync bf16 tensor cores.
// D[128 vox, 96 oc] = Y[128 vox, 96 fv] @ W[96 oc, 96 fv]^T
// bf16 hi/lo split, 3 passes (Ah*Bh + Al*Bh + Ah*Bl), fp32 accum.
// 4 voxel tiles per block; W staged once per block.
// ---------------------------------------------------------------------------
#define PA32 52     // A pitch in u32 (104 bf16)
#define PB32 52     // B pitch in u32
#define PD   132    // D staging pitch (floats)

#define OFF_AH 0
#define OFF_AL 26624                 // 128*52*4
#define OFF_BH 53248
#define OFF_BL 73216                 // + 96*52*4
#define MIX_SMEM_TOTAL 93184         // + 96*52*4

#define MIX_TILES 4

__device__ __forceinline__ void mma16816(float* c, const uint32_t a[4],
                                         uint32_t b0, uint32_t b1) {
    asm volatile(
        "mma.sync.aligned.m16n8k16.row.col.f32.bf16.bf16.f32 "
        "{%0,%1,%2,%3}, {%4,%5,%6,%7}, {%8,%9}, {%0,%1,%2,%3};"
        : "+f"(c[0]), "+f"(c[1]), "+f"(c[2]), "+f"(c[3])
        : "r"(a[0]), "r"(a[1]), "r"(a[2]), "r"(a[3]), "r"(b0), "r"(b1));
}

// split float pair into truncated-bf16 hi pair + rounded-bf16 lo pair
__device__ __forceinline__ void split2(float y0, float y1, uint32_t& hi, uint32_t& lo) {
    uint32_t u0 = __float_as_uint(y0), u1 = __float_as_uint(y1);
    float h0 = __uint_as_float(u0 & 0xFFFF0000u);
    float h1 = __uint_as_float(u1 & 0xFFFF0000u);
    hi = __byte_perm(u0, u1, 0x7632);
    asm("cvt.rn.bf16x2.f32 %0, %1, %2;" : "=r"(lo) : "f"(y1 - h1), "f"(y0 - h0));
}

__global__ __launch_bounds__(128) void mix_kernel(
    const float* __restrict__ bias, float* __restrict__ out)
{
    extern __shared__ __align__(16) char smem[];
    uint32_t* Ah = (uint32_t*)(smem + OFF_AH);
    uint32_t* Al = (uint32_t*)(smem + OFF_AL);
    uint32_t* Bh = (uint32_t*)(smem + OFF_BH);
    uint32_t* Bl = (uint32_t*)(smem + OFF_BL);

    int t    = threadIdx.x;
    int wid  = t >> 5;
    int lane = t & 31;
    int g    = lane >> 2;      // group row
    int q    = lane & 3;       // thread in group

    // ---- stage W (hi/lo bf16) once per block ----
    for (int idx = t; idx < CH * 48; idx += 128) {
        int oc = idx / 48, j = idx % 48;
        float w0 = g_fwm[oc * CH + 2 * j];
        float w1 = g_fwm[oc * CH + 2 * j + 1];
        uint32_t hi, lo;
        split2(w0, w1, hi, lo);
        Bh[oc * PB32 + j] = hi;
        Bl[oc * PB32 + j] = lo;
    }
    float bv[8];
    #pragma unroll
    for (int i = 0; i < 8; i++) bv[i] = bias[i];

    for (int it = 0; it < MIX_TILES; it++) {
        int tv = blockIdx.x * MIX_TILES + it;   // 0..4095
        int b  = tv >> 11;
        int p0 = (tv & 2047) * 128;

        // ---- stage Y tile (hi/lo bf16) with XOR-swizzled columns ----
        {
            const float* yb = g_y + (size_t)b * CH * VOX + p0 + t;
            int sw = (t >> 3) & 3;
            #pragma unroll 8
            for (int cp = 0; cp < 48; cp++) {
                float y0 = yb[(size_t)(2 * cp) * VOX];
                float y1 = yb[(size_t)(2 * cp + 1) * VOX];
                uint32_t hi, lo;
                split2(y0, y1, hi, lo);
                Ah[t * PA32 + (cp ^ sw)] = hi;
                Al[t * PA32 + (cp ^ sw)] = lo;
            }
        }
        __syncthreads();

        // ---- MMA: each warp computes 32 voxels x 96 oc ----
        int m0 = wid * 32;
        float acc[2][12][4];
        #pragma unroll
        for (int mt = 0; mt < 2; mt++)
            #pragma unroll
            for (int n = 0; n < 12; n++)
                #pragma unroll
                for (int i = 0; i < 4; i++) acc[mt][n][i] = 0.f;

        const uint32_t* Asrc[3] = { Ah, Al, Ah };
        const uint32_t* Bsrc[3] = { Bh, Bh, Bl };
        #pragma unroll 1
        for (int pass = 0; pass < 3; pass++) {
            const uint32_t* As = Asrc[pass];
            const uint32_t* Bs = Bsrc[pass];
            #pragma unroll
            for (int k = 0; k < 6; k++) {
                int c0 = 8 * k + q;
                uint32_t af[2][4];
                #pragma unroll
                for (int mt = 0; mt < 2; mt++) {
                    int row0 = m0 + mt * 16 + g;
                    int s0 = 2 * mt, s1 = 2 * mt + 1;
                    af[mt][0] = As[row0 * PA32       + (c0 ^ s0)];
                    af[mt][1] = As[(row0 + 8) * PA32 + (c0 ^ s1)];
                    af[mt][2] = As[row0 * PA32       + ((c0 + 4) ^ s0)];
                    af[mt][3] = As[(row0 + 8) * PA32 + ((c0 + 4) ^ s1)];
                }
                #pragma unroll
                for (int n = 0; n < 12; n++) {
                    const uint32_t* pb = Bs + (n * 8 + g) * PB32 + 8 * k + q;
                    uint32_t b0 = pb[0];
                    uint32_t b1 = pb[4];
                    mma16816(acc[0][n], af[0], b0, b1);
                    mma16816(acc[1][n], af[1], b0, b1);
                }
            }
        }

        // ---- stage D to smem (reuse A region), then coalesced writeback ----
        __syncthreads();
        float* D = (float*)(smem + OFF_AH);
        #pragma unroll
        for (int mt = 0; mt < 2; mt++) {
            int r1 = m0 + mt * 16 + g;
            #pragma unroll
            for (int n = 0; n < 12; n++) {
                int ocb = n * 8 + 2 * q;
                D[(ocb)     * PD + r1]     = acc[mt][n][0];
                D[(ocb + 1) * PD + r1]     = acc[mt][n][1];
                D[(ocb)     * PD + r1 + 8] = acc[mt][n][2];
                D[(ocb + 1) * PD + r1 + 8] = acc[mt][n][3];
            }
        }
        __syncthreads();

        float* ob = out + (size_t)b * CH * VOX + p0 + t;
        #pragma unroll
        for (int c = 0; c < CH; c++)
            ob[(size_t)c * VOX] = D[c * PD + t] + bv[c / 12];
        __syncthreads();
    }
}

// ---------------------------------------------------------------------------
extern "C" void kernel_launch(void* const* d_in, const int* in_sizes, int n_in,
                              void* d_out, int out_size)
{
    const float* x    = (const float*)d_in[0];
    const float* sp   = (const float*)d_in[1];
    const float* sph  = (const float*)d_in[2];
    const float* bw1  = (const float*)d_in[3];
    const float* bb1  = (const float*)d_in[4];
    const float* bw2  = (const float*)d_in[5];
    const float* bb2  = (const float*)d_in[6];
    const float* bw3  = (const float*)d_in[7];
    const float* fw1  = (const float*)d_in[8];
    const float* fb1  = (const float*)d_in[9];
    const float* fw2  = (const float*)d_in[10];
    const float* fb2  = (const float*)d_in[11];
    const float* fw3  = (const float*)d_in[12];
    const float* bias = (const float*)d_in[13];

    cudaFuncSetAttribute(mix_kernel, cudaFuncAttributeMaxDynamicSharedMemorySize,
                         MIX_SMEM_TOTAL);

    weights_kernel<<<13, 128>>>(sp, sph, bw1, bb1, bw2, bb2, bw3,
                                fw1, fb1, fw2, fb2, fw3);

    dim3 gA(128, CH, 2);
    conv_kernel<<<gA, 256>>>(x);

    mix_kernel<<<4096 / MIX_TILES, 128, MIX_SMEM_TOTAL>>>(bias, (float*)d_out);
}